// round 6
// baseline (speedup 1.0000x reference)
#include <cuda_runtime.h>
#include <math.h>

#define Bn 16
#define Nn 25000
#define Mn 64
#define TILE 256
#define NTILES ((Nn + TILE - 1) / TILE)   // 98
#define NBLK (NTILES * Bn)                // 1568

// ---- scratch (no allocations allowed; zero-initialized at load) ----
// g_pack maintained by atomicMax; g_pack/g_focal/g_ctr reset by the tail
// phase every call, so the kernel is deterministic across graph replays.
__device__ unsigned long long g_pack[Bn*Mn];   // (iou_bits<<32) | ~idx
__device__ float g_focal[Bn];
__device__ unsigned int g_ctr = 0;

__global__ __launch_bounds__(256) void k_all(const float* __restrict__ preds,
                                             const float* __restrict__ targets,
                                             float* __restrict__ out) {
    const int b    = blockIdx.y;
    const int base = blockIdx.x * TILE;
    const int tid  = threadIdx.x;
    const int lane = tid & 31;
    const int warp = tid >> 5;

    // phase-1 shared
    __shared__ float4 s_box[TILE];
    __shared__ float  s_area[TILE];
    __shared__ unsigned long long s_m[8*Mn];
    __shared__ float  s_red[16];
    __shared__ int    s_last;
    // tail shared
    __shared__ float  s_biou[Bn*Mn];
    __shared__ int    s_bidx[Bn*Mn];
    __shared__ float  s_ci[Bn*Mn], s_fd[Bn*Mn];
    __shared__ unsigned char s_ok[Bn*Mn];

    // ================= phase 1: IoU argmax + focal partials =================
    const float4 t0 = __ldg((const float4*)targets + (b*Mn + lane));
    const float4 t1 = __ldg((const float4*)targets + (b*Mn + lane + 32));
    const float ta0 = (t0.z - t0.x) * (t0.w - t0.y);
    const float ta1 = (t1.z - t1.x) * (t1.w - t1.y);

    const int cnt = min(TILE, Nn - base);
    float facc = 0.f;
    {
        // stage + convert + focal(target=0): one pred per thread
        float x1, y1, x2, y2, area;
        if (tid < cnt) {
            const float* pr = preds + ((size_t)b * Nn + base + tid) * 5;
            float cx = pr[0], cy = pr[1];
            float w = fmaxf(pr[2], 1e-4f), h = fmaxf(pr[3], 1e-4f);
            float conf = pr[4];
            x1 = cx - 0.5f * w; x2 = cx + 0.5f * w;
            y1 = cy - 0.5f * h; y2 = cy + 0.5f * h;
            area = (x2 - x1) * (y2 - y1);
            float p  = 1.f / (1.f + expf(-conf));
            float ce = fmaxf(conf, 0.f) + log1pf(expf(-fabsf(conf)));
            float pt = fminf(fmaxf(1.f - p, 1e-6f), 1.f - 1e-6f);
            float om = 1.f - pt;
            facc = 0.75f * om * om * ce;
        } else {
            // pad: degenerate far box -> iou exactly 0; idx > all real cids,
            // so it loses every tie at the pack/merge stage.
            x1 = y1 = x2 = y2 = -3e8f; area = 0.f;
        }
        s_box[tid]  = make_float4(x1, y1, x2, y2);
        s_area[tid] = area;
    }
    __syncthreads();

    // strict > over increasing k keeps the FIRST max within this warp's stream
    float best0 = -1.f, best1 = -1.f;
    int   bk0 = 0, bk1 = 0;
    const int pbase = base + warp * 32;

    #pragma unroll
    for (int k = 0; k < 32; k++) {
        const float4 bx = s_box[warp * 32 + k];   // broadcast LDS
        const float  ar = s_area[warp * 32 + k];
        {
            float iw = fmaxf(fminf(bx.z, t0.z) - fmaxf(bx.x, t0.x), 0.f);
            float ih = fmaxf(fminf(bx.w, t0.w) - fmaxf(bx.y, t0.y), 0.f);
            float inter = iw * ih;
            float iou = __fdividef(inter, ar + ta0 - inter);
            bool p = iou > best0;
            best0 = p ? iou : best0;
            bk0   = p ? (pbase + k) : bk0;
        }
        {
            float iw = fmaxf(fminf(bx.z, t1.z) - fmaxf(bx.x, t1.x), 0.f);
            float ih = fmaxf(fminf(bx.w, t1.w) - fmaxf(bx.y, t1.y), 0.f);
            float inter = iw * ih;
            float iou = __fdividef(inter, ar + ta1 - inter);
            bool p = iou > best1;
            best1 = p ? iou : best1;
            bk1   = p ? (pbase + k) : bk1;
        }
    }

    // pack: higher iou wins; on tie, ~idx makes SMALLER idx win
    s_m[warp*Mn + lane] =
        ((unsigned long long)__float_as_uint(best0) << 32) | (unsigned)(~bk0);
    s_m[warp*Mn + lane + 32] =
        ((unsigned long long)__float_as_uint(best1) << 32) | (unsigned)(~bk1);

    // focal warp-reduce
    #pragma unroll
    for (int off = 16; off; off >>= 1)
        facc += __shfl_xor_sync(0xffffffffu, facc, off);
    if (lane == 0) s_red[warp] = facc;
    __syncthreads();

    if (tid < Mn) {
        unsigned long long bv = 0ull;
        #pragma unroll
        for (int w = 0; w < 8; w++) {
            unsigned long long v = s_m[w*Mn + tid];
            bv = (v > bv) ? v : bv;
        }
        atomicMax(&g_pack[b*Mn + tid], bv);
    }
    if (tid == 64) {
        float s = 0.f;
        #pragma unroll
        for (int w = 0; w < 8; w++) s += s_red[w];
        atomicAdd(&g_focal[b], s);
    }

    // ================= phase 2: last finished block runs the tail ===========
    __threadfence();
    if (tid == 0) {
        unsigned int old = atomicAdd(&g_ctr, 1u);
        s_last = (old == NBLK - 1) ? 1 : 0;
    }
    __syncthreads();
    if (!s_last) return;
    __threadfence();

    // 2a) load the globally-merged argmax per (b,m); reset scratch
    #pragma unroll
    for (int i = 0; i < 4; i++) {
        const int p = tid + i * 256;               // p = b*64 + m
        unsigned long long v = g_pack[p];
        g_pack[p] = 0ull;                          // reset for next replay
        s_biou[p] = __uint_as_float((unsigned)(v >> 32));
        s_bidx[p] = (int)(~(unsigned)v);
    }
    if (tid == 0) g_ctr = 0;
    __syncthreads();

    // 2b) greedy dedup (closed form) + CIoU + focal correction
    #pragma unroll
    for (int i = 0; i < 4; i++) {
        const int p  = tid + i * 256;
        const int b2 = p >> 6;
        const int m  = p & 63;
        const float iou_b = s_biou[p];
        const int   idx   = s_bidx[p];

        bool ok = iou_b > 0.2f;
        if (ok) {
            for (int mp = 0; mp < m; mp++)
                if (s_bidx[(b2<<6) + mp] == idx && s_biou[(b2<<6) + mp] > 0.2f) { ok = false; break; }
        }

        float ci = 0.f, fd = 0.f;
        if (ok) {
            const float* pr = preds + ((size_t)b2*Nn + idx) * 5;
            float cx = pr[0], cy = pr[1];
            float w = fmaxf(pr[2], 1e-4f), h = fmaxf(pr[3], 1e-4f);
            float conf = pr[4];
            float x1p = cx - 0.5f*w, x2p = cx + 0.5f*w;
            float y1p = cy - 0.5f*h, y2p = cy + 0.5f*h;
            float4 t = __ldg((const float4*)targets + p);
            float x1t = t.x, y1t = t.y, x2t = t.z, y2t = t.w;

            float inter = fmaxf(fminf(x2p,x2t) - fmaxf(x1p,x1t), 0.f)
                        * fmaxf(fminf(y2p,y2t) - fmaxf(y1p,y1t), 0.f);
            float un  = (x2p-x1p)*(y2p-y1p) + (x2t-x1t)*(y2t-y1t) - inter;
            float iou = inter / (un + 1e-7f);
            float cw = fmaxf(x2p,x2t) - fminf(x1p,x1t);
            float ch = fmaxf(y2p,y2t) - fminf(y1p,y1t);
            float diag = cw*cw + ch*ch + 1e-7f;
            float dx = x1p + x2p - x1t - x2t;
            float dy = y1p + y2p - y1t - y2t;
            float centers = (dx*dx + dy*dy) * 0.25f;
            float wp = x2p - x1p, hp = y2p - y1p;
            float wt = x2t - x1t, ht = y2t - y1t;
            float dv = atanf(wt/ht) - atanf(wp/hp);
            float vv = (float)(4.0/(M_PI*M_PI)) * dv * dv;
            float alpha = vv / (1.f - iou + vv + 1e-7f);
            ci = 1.f - iou + centers/diag + alpha*vv;

            // focal(target=1) - focal(target=0) correction
            float pp  = 1.f / (1.f + expf(-conf));
            float l1e = log1pf(expf(-fabsf(conf)));
            float ce1 = fmaxf(conf, 0.f) - conf + l1e;
            float ce0 = fmaxf(conf, 0.f) + l1e;
            float pt1 = fminf(fmaxf(pp,       1e-6f), 1.f - 1e-6f);
            float pt0 = fminf(fmaxf(1.f - pp, 1e-6f), 1.f - 1e-6f);
            float a1 = 1.f - pt1, a0 = 1.f - pt0;
            fd = 0.25f*a1*a1*ce1 - 0.75f*a0*a0*ce0;
        }
        s_ci[p] = ci; s_fd[p] = fd; s_ok[p] = ok ? 1 : 0;
    }
    __syncthreads();

    // 2c) per-image loss, final mean, scratch reset
    if (tid < Bn) {
        float sc = 0.f, sf = 0.f; int n = 0;
        #pragma unroll
        for (int i = 0; i < Mn; i++) {
            sc += s_ci[(tid<<6) + i];
            sf += s_fd[(tid<<6) + i];
            n  += s_ok[(tid<<6) + i];
        }
        float conf_loss = (g_focal[tid] + sf) / (float)Nn;
        g_focal[tid] = 0.f;                // reset for next replay
        float box = (n > 0) ? sc / (float)n : 0.f;
        s_red[tid] = conf_loss + box;
    }
    __syncthreads();
    if (tid == 0) {
        float s = 0.f;
        #pragma unroll
        for (int i = 0; i < Bn; i++) s += s_red[i];
        out[0] = s * (1.f / (float)Bn);
    }
}

extern "C" void kernel_launch(void* const* d_in, const int* in_sizes, int n_in,
                              void* d_out, int out_size) {
    const float* preds   = (const float*)d_in[0];
    const float* targets = (const float*)d_in[1];
    float* out = (float*)d_out;
    k_all<<<dim3(NTILES, Bn), 256>>>(preds, targets, out);
}

// round 7
// speedup vs baseline: 2.3262x; 2.3262x over previous
#include <cuda_runtime.h>
#include <math.h>

#define Bn 16
#define Nn 25000
#define Mn 64
#define TILE 256
#define NTILES ((Nn + TILE - 1) / TILE)   // 98

// ---- scratch (no allocations allowed; zero-initialized at load) ----
// g_pack maintained by atomicMax (idempotent across replays), reset by k_final.
__device__ unsigned long long g_pack[Bn*Mn];   // (iou_bits<<32) | ~idx
__device__ float g_focal[Bn];

// One 256-pred tile per block. Lane l of each warp owns targets l and l+32 in
// registers; each warp streams its 32 preds of the tile via broadcast LDS.
// Running argmax is scalar branchless: FSETP + SEL pairs.
__global__ __launch_bounds__(256) void k_main(const float* __restrict__ preds,
                                              const float* __restrict__ targets,
                                              float* __restrict__ out) {
    const int b    = blockIdx.y;
    const int base = blockIdx.x * TILE;
    const int tid  = threadIdx.x;
    const int lane = tid & 31;
    const int warp = tid >> 5;

    __shared__ float4 s_box[TILE];
    __shared__ float  s_area[TILE];
    __shared__ unsigned long long s_m[8*Mn];
    __shared__ float  s_red[8];

    // zero the output for k_final's atomicAdd (stream order makes this safe)
    if (b == 0 && blockIdx.x == 0 && tid == 96) out[0] = 0.f;

    const float4 t0 = __ldg((const float4*)targets + (b*Mn + lane));
    const float4 t1 = __ldg((const float4*)targets + (b*Mn + lane + 32));
    const float ta0 = (t0.z - t0.x) * (t0.w - t0.y);
    const float ta1 = (t1.z - t1.x) * (t1.w - t1.y);

    const int cnt = min(TILE, Nn - base);
    float facc = 0.f;
    {
        // stage + convert + focal(target=0): one pred per thread
        float x1, y1, x2, y2, area;
        if (tid < cnt) {
            const float* pr = preds + ((size_t)b * Nn + base + tid) * 5;
            float cx = pr[0], cy = pr[1];
            float w = fmaxf(pr[2], 1e-4f), h = fmaxf(pr[3], 1e-4f);
            float conf = pr[4];
            x1 = cx - 0.5f * w; x2 = cx + 0.5f * w;
            y1 = cy - 0.5f * h; y2 = cy + 0.5f * h;
            area = (x2 - x1) * (y2 - y1);
            float p  = 1.f / (1.f + expf(-conf));
            float ce = fmaxf(conf, 0.f) + log1pf(expf(-fabsf(conf)));
            float pt = fminf(fmaxf(1.f - p, 1e-6f), 1.f - 1e-6f);
            float om = 1.f - pt;
            facc = 0.75f * om * om * ce;
        } else {
            // pad: degenerate far box -> iou exactly 0; idx > all real cids,
            // so it loses every tie at the pack/merge stage.
            x1 = y1 = x2 = y2 = -3e8f; area = 0.f;
        }
        s_box[tid]  = make_float4(x1, y1, x2, y2);
        s_area[tid] = area;
    }
    __syncthreads();

    // strict > over increasing k keeps the FIRST max within this warp's stream
    float best0 = -1.f, best1 = -1.f;
    int   bk0 = 0, bk1 = 0;
    const int pbase = base + warp * 32;

    #pragma unroll
    for (int k = 0; k < 32; k++) {
        const float4 bx = s_box[warp * 32 + k];   // broadcast LDS
        const float  ar = s_area[warp * 32 + k];
        {
            float iw = fmaxf(fminf(bx.z, t0.z) - fmaxf(bx.x, t0.x), 0.f);
            float ih = fmaxf(fminf(bx.w, t0.w) - fmaxf(bx.y, t0.y), 0.f);
            float inter = iw * ih;
            float iou = __fdividef(inter, ar + ta0 - inter);
            bool p = iou > best0;
            best0 = p ? iou : best0;
            bk0   = p ? (pbase + k) : bk0;
        }
        {
            float iw = fmaxf(fminf(bx.z, t1.z) - fmaxf(bx.x, t1.x), 0.f);
            float ih = fmaxf(fminf(bx.w, t1.w) - fmaxf(bx.y, t1.y), 0.f);
            float inter = iw * ih;
            float iou = __fdividef(inter, ar + ta1 - inter);
            bool p = iou > best1;
            best1 = p ? iou : best1;
            bk1   = p ? (pbase + k) : bk1;
        }
    }

    // pack: higher iou wins; on tie, ~idx makes SMALLER idx win
    s_m[warp*Mn + lane] =
        ((unsigned long long)__float_as_uint(best0) << 32) | (unsigned)(~bk0);
    s_m[warp*Mn + lane + 32] =
        ((unsigned long long)__float_as_uint(best1) << 32) | (unsigned)(~bk1);

    // focal warp-reduce
    #pragma unroll
    for (int off = 16; off; off >>= 1)
        facc += __shfl_xor_sync(0xffffffffu, facc, off);
    if (lane == 0) s_red[warp] = facc;
    __syncthreads();

    if (tid < Mn) {
        unsigned long long bv = 0ull;
        #pragma unroll
        for (int w = 0; w < 8; w++) {
            unsigned long long v = s_m[w*Mn + tid];
            bv = (v > bv) ? v : bv;
        }
        atomicMax(&g_pack[b*Mn + tid], bv);
    }
    if (tid == 64) {
        float s = 0.f;
        #pragma unroll
        for (int w = 0; w < 8; w++) s += s_red[w];
        atomicAdd(&g_focal[b], s);
    }
}

// One image per block (16 blocks x 64 threads): greedy dedup (closed form),
// CIoU, focal corrections, per-image loss, atomicAdd of mean contribution.
// Also resets scratch for the next graph replay.
__global__ __launch_bounds__(64) void k_final(const float* __restrict__ preds,
                                              const float* __restrict__ targets,
                                              float* __restrict__ out) {
    const int b = blockIdx.x;
    const int m = threadIdx.x;

    __shared__ float s_iou[Mn];
    __shared__ int   s_idx[Mn];
    __shared__ float s_ci[Mn], s_fd[Mn];
    __shared__ unsigned char s_ok[Mn];

    unsigned long long v = g_pack[b*Mn + m];
    g_pack[b*Mn + m] = 0ull;               // reset for next replay
    float iou_b = __uint_as_float((unsigned)(v >> 32));
    int   idx   = (int)(~(unsigned)v);
    s_iou[m] = iou_b;
    s_idx[m] = idx;
    __syncthreads();

    bool ok = iou_b > 0.2f;
    if (ok) {
        for (int mp = 0; mp < m; mp++)
            if (s_idx[mp] == idx && s_iou[mp] > 0.2f) { ok = false; break; }
    }

    float ci = 0.f, fd = 0.f;
    if (ok) {
        const float* pr = preds + ((size_t)b*Nn + idx) * 5;
        float cx = pr[0], cy = pr[1];
        float w = fmaxf(pr[2], 1e-4f), h = fmaxf(pr[3], 1e-4f);
        float conf = pr[4];
        float x1p = cx - 0.5f*w, x2p = cx + 0.5f*w;
        float y1p = cy - 0.5f*h, y2p = cy + 0.5f*h;
        float4 t = __ldg((const float4*)targets + (b*Mn + m));
        float x1t = t.x, y1t = t.y, x2t = t.z, y2t = t.w;

        float inter = fmaxf(fminf(x2p,x2t) - fmaxf(x1p,x1t), 0.f)
                    * fmaxf(fminf(y2p,y2t) - fmaxf(y1p,y1t), 0.f);
        float un  = (x2p-x1p)*(y2p-y1p) + (x2t-x1t)*(y2t-y1t) - inter;
        float iou = inter / (un + 1e-7f);
        float cw = fmaxf(x2p,x2t) - fminf(x1p,x1t);
        float ch = fmaxf(y2p,y2t) - fminf(y1p,y1t);
        float diag = cw*cw + ch*ch + 1e-7f;
        float dx = x1p + x2p - x1t - x2t;
        float dy = y1p + y2p - y1t - y2t;
        float centers = (dx*dx + dy*dy) * 0.25f;
        float wp = x2p - x1p, hp = y2p - y1p;
        float wt = x2t - x1t, ht = y2t - y1t;
        float dv = atanf(wt/ht) - atanf(wp/hp);
        float vv = (float)(4.0/(M_PI*M_PI)) * dv * dv;
        float alpha = vv / (1.f - iou + vv + 1e-7f);
        ci = 1.f - iou + centers/diag + alpha*vv;

        // focal(target=1) - focal(target=0) correction for this pred
        float pp  = 1.f / (1.f + expf(-conf));
        float l1e = log1pf(expf(-fabsf(conf)));
        float ce1 = fmaxf(conf, 0.f) - conf + l1e;
        float ce0 = fmaxf(conf, 0.f) + l1e;
        float pt1 = fminf(fmaxf(pp,       1e-6f), 1.f - 1e-6f);
        float pt0 = fminf(fmaxf(1.f - pp, 1e-6f), 1.f - 1e-6f);
        float a1 = 1.f - pt1, a0 = 1.f - pt0;
        fd = 0.25f*a1*a1*ce1 - 0.75f*a0*a0*ce0;
    }
    s_ci[m] = ci; s_fd[m] = fd; s_ok[m] = ok ? 1 : 0;
    __syncthreads();

    if (m == 0) {
        float sc = 0.f, sf = 0.f; int n = 0;
        #pragma unroll
        for (int i = 0; i < Mn; i++) {
            sc += s_ci[i]; sf += s_fd[i]; n += s_ok[i];
        }
        float conf_loss = (g_focal[b] + sf) / (float)Nn;
        g_focal[b] = 0.f;                  // reset for next replay
        float box = (n > 0) ? sc / (float)n : 0.f;
        atomicAdd(out, (conf_loss + box) * (1.f / (float)Bn));
    }
}

extern "C" void kernel_launch(void* const* d_in, const int* in_sizes, int n_in,
                              void* d_out, int out_size) {
    const float* preds   = (const float*)d_in[0];
    const float* targets = (const float*)d_in[1];
    float* out = (float*)d_out;

    k_main <<<dim3(NTILES, Bn), 256>>>(preds, targets, out);
    k_final<<<Bn, Mn>>>(preds, targets, out);
}

// round 8
// speedup vs baseline: 3.7785x; 1.6243x over previous
#include <cuda_runtime.h>
#include <math.h>

#define Bn 16
#define Nn 25000
#define Mn 64
#define TILE 256
#define NTILES ((Nn + TILE - 1) / TILE)   // 98

// ---- scratch (no allocations allowed; zero-initialized at load) ----
// g_pack maintained by atomicMax (idempotent across replays), reset by k_final.
__device__ unsigned long long g_pack[Bn*Mn];   // (iou_bits<<32) | ~idx
__device__ float g_focal[Bn];

// One 256-pred tile per block. Lane l of each warp owns targets l and l+32 in
// registers; each warp streams its 32 preds of the tile via broadcast LDS.
// Running argmax is scalar branchless: FSETP + SEL pairs.  (UNCHANGED — 24.1us)
__global__ __launch_bounds__(256) void k_main(const float* __restrict__ preds,
                                              const float* __restrict__ targets,
                                              float* __restrict__ out) {
    const int b    = blockIdx.y;
    const int base = blockIdx.x * TILE;
    const int tid  = threadIdx.x;
    const int lane = tid & 31;
    const int warp = tid >> 5;

    __shared__ float4 s_box[TILE];
    __shared__ float  s_area[TILE];
    __shared__ unsigned long long s_m[8*Mn];
    __shared__ float  s_red[8];

    // zero the output for k_final's atomicAdd (stream order makes this safe)
    if (b == 0 && blockIdx.x == 0 && tid == 96) out[0] = 0.f;

    const float4 t0 = __ldg((const float4*)targets + (b*Mn + lane));
    const float4 t1 = __ldg((const float4*)targets + (b*Mn + lane + 32));
    const float ta0 = (t0.z - t0.x) * (t0.w - t0.y);
    const float ta1 = (t1.z - t1.x) * (t1.w - t1.y);

    const int cnt = min(TILE, Nn - base);
    float facc = 0.f;
    {
        // stage + convert + focal(target=0): one pred per thread
        float x1, y1, x2, y2, area;
        if (tid < cnt) {
            const float* pr = preds + ((size_t)b * Nn + base + tid) * 5;
            float cx = pr[0], cy = pr[1];
            float w = fmaxf(pr[2], 1e-4f), h = fmaxf(pr[3], 1e-4f);
            float conf = pr[4];
            x1 = cx - 0.5f * w; x2 = cx + 0.5f * w;
            y1 = cy - 0.5f * h; y2 = cy + 0.5f * h;
            area = (x2 - x1) * (y2 - y1);
            float p  = 1.f / (1.f + expf(-conf));
            float ce = fmaxf(conf, 0.f) + log1pf(expf(-fabsf(conf)));
            float pt = fminf(fmaxf(1.f - p, 1e-6f), 1.f - 1e-6f);
            float om = 1.f - pt;
            facc = 0.75f * om * om * ce;
        } else {
            // pad: degenerate far box -> iou exactly 0; idx > all real cids,
            // so it loses every tie at the pack/merge stage.
            x1 = y1 = x2 = y2 = -3e8f; area = 0.f;
        }
        s_box[tid]  = make_float4(x1, y1, x2, y2);
        s_area[tid] = area;
    }
    __syncthreads();

    // strict > over increasing k keeps the FIRST max within this warp's stream
    float best0 = -1.f, best1 = -1.f;
    int   bk0 = 0, bk1 = 0;
    const int pbase = base + warp * 32;

    #pragma unroll
    for (int k = 0; k < 32; k++) {
        const float4 bx = s_box[warp * 32 + k];   // broadcast LDS
        const float  ar = s_area[warp * 32 + k];
        {
            float iw = fmaxf(fminf(bx.z, t0.z) - fmaxf(bx.x, t0.x), 0.f);
            float ih = fmaxf(fminf(bx.w, t0.w) - fmaxf(bx.y, t0.y), 0.f);
            float inter = iw * ih;
            float iou = __fdividef(inter, ar + ta0 - inter);
            bool p = iou > best0;
            best0 = p ? iou : best0;
            bk0   = p ? (pbase + k) : bk0;
        }
        {
            float iw = fmaxf(fminf(bx.z, t1.z) - fmaxf(bx.x, t1.x), 0.f);
            float ih = fmaxf(fminf(bx.w, t1.w) - fmaxf(bx.y, t1.y), 0.f);
            float inter = iw * ih;
            float iou = __fdividef(inter, ar + ta1 - inter);
            bool p = iou > best1;
            best1 = p ? iou : best1;
            bk1   = p ? (pbase + k) : bk1;
        }
    }

    // pack: higher iou wins; on tie, ~idx makes SMALLER idx win
    s_m[warp*Mn + lane] =
        ((unsigned long long)__float_as_uint(best0) << 32) | (unsigned)(~bk0);
    s_m[warp*Mn + lane + 32] =
        ((unsigned long long)__float_as_uint(best1) << 32) | (unsigned)(~bk1);

    // focal warp-reduce
    #pragma unroll
    for (int off = 16; off; off >>= 1)
        facc += __shfl_xor_sync(0xffffffffu, facc, off);
    if (lane == 0) s_red[warp] = facc;
    __syncthreads();

    if (tid < Mn) {
        unsigned long long bv = 0ull;
        #pragma unroll
        for (int w = 0; w < 8; w++) {
            unsigned long long v = s_m[w*Mn + tid];
            bv = (v > bv) ? v : bv;
        }
        atomicMax(&g_pack[b*Mn + tid], bv);
    }
    if (tid == 64) {
        float s = 0.f;
        #pragma unroll
        for (int w = 0; w < 8; w++) s += s_red[w];
        atomicAdd(&g_focal[b], s);
    }
}

// Latency-lean tail: one image per block (16 x 64). All loads prefetched
// before the dedup; unconditional compute with masked accumulate; fast-math
// intrinsics (tolerance budget 1e-3, perturbation ~1e-6); shuffle reductions.
__global__ __launch_bounds__(64) void k_final(const float* __restrict__ preds,
                                              const float* __restrict__ targets,
                                              float* __restrict__ out) {
    const int b    = blockIdx.x;
    const int m    = threadIdx.x;
    const int lane = m & 31;
    const int w    = m >> 5;

    __shared__ float s_iou[Mn];
    __shared__ int   s_idx[Mn];
    __shared__ float s_c[2], s_f[2];
    __shared__ int   s_n[2];

    // --- independent prefetches (issue ASAP) ---
    const float gf = g_focal[b];                         // broadcast load
    unsigned long long v = g_pack[b*Mn + m];
    g_pack[b*Mn + m] = 0ull;                             // reset for next replay
    const float iou_b = __uint_as_float((unsigned)(v >> 32));
    int idx = (int)(~(unsigned)v);
    idx = min(max(idx, 0), Nn - 1);                      // always valid post-k_main

    // prefetch the matched pred (overlaps the dedup below)
    const float* pr = preds + ((size_t)b*Nn + idx) * 5;
    const float cx = pr[0], cy = pr[1];
    const float pw = fmaxf(pr[2], 1e-4f), ph = fmaxf(pr[3], 1e-4f);
    const float conf = pr[4];
    const float4 t = __ldg((const float4*)targets + (b*Mn + m));

    s_iou[m] = iou_b;
    s_idx[m] = idx;
    __syncthreads();

    // greedy dedup, closed form
    bool ok = iou_b > 0.2f;
    for (int mp = 0; mp < m; mp++)
        ok = ok && !(s_idx[mp] == idx && s_iou[mp] > 0.2f);

    // --- unconditional CIoU + focal correction, masked at accumulate ---
    const float x1p = cx - 0.5f*pw, x2p = cx + 0.5f*pw;
    const float y1p = cy - 0.5f*ph, y2p = cy + 0.5f*ph;
    const float x1t = t.x, y1t = t.y, x2t = t.z, y2t = t.w;

    float inter = fmaxf(fminf(x2p,x2t) - fmaxf(x1p,x1t), 0.f)
                * fmaxf(fminf(y2p,y2t) - fmaxf(y1p,y1t), 0.f);
    float un  = (x2p-x1p)*(y2p-y1p) + (x2t-x1t)*(y2t-y1t) - inter;
    float iou = __fdividef(inter, un + 1e-7f);
    float cw = fmaxf(x2p,x2t) - fminf(x1p,x1t);
    float ch = fmaxf(y2p,y2t) - fminf(y1p,y1t);
    float diag = cw*cw + ch*ch + 1e-7f;
    float dx = x1p + x2p - x1t - x2t;
    float dy = y1p + y2p - y1t - y2t;
    float centers = (dx*dx + dy*dy) * 0.25f;
    float wp = x2p - x1p, hp = y2p - y1p;
    float wt = x2t - x1t, ht = y2t - y1t;
    float dv = atanf(__fdividef(wt, ht)) - atanf(__fdividef(wp, hp));
    float vv = (float)(4.0/(M_PI*M_PI)) * dv * dv;
    float alpha = __fdividef(vv, 1.f - iou + vv + 1e-7f);
    float ci = 1.f - iou + __fdividef(centers, diag) + alpha*vv;

    // focal(target=1) - focal(target=0) correction
    float pp  = __fdividef(1.f, 1.f + __expf(-conf));
    float l1e = __logf(1.f + __expf(-fabsf(conf)));
    float ce1 = fmaxf(conf, 0.f) - conf + l1e;
    float ce0 = fmaxf(conf, 0.f) + l1e;
    float pt1 = fminf(fmaxf(pp,       1e-6f), 1.f - 1e-6f);
    float pt0 = fminf(fmaxf(1.f - pp, 1e-6f), 1.f - 1e-6f);
    float a1 = 1.f - pt1, a0 = 1.f - pt0;
    float fd = 0.25f*a1*a1*ce1 - 0.75f*a0*a0*ce0;

    const float msk = ok ? 1.f : 0.f;
    ci *= msk; fd *= msk;
    int n = ok ? 1 : 0;

    // two-warp shuffle reduction
    #pragma unroll
    for (int off = 16; off; off >>= 1) {
        ci += __shfl_xor_sync(0xffffffffu, ci, off);
        fd += __shfl_xor_sync(0xffffffffu, fd, off);
        n  += __shfl_xor_sync(0xffffffffu, n,  off);
    }
    if (lane == 0) { s_c[w] = ci; s_f[w] = fd; s_n[w] = n; }
    __syncthreads();

    if (m == 0) {
        float sc = s_c[0] + s_c[1];
        float sf = s_f[0] + s_f[1];
        int   nn = s_n[0] + s_n[1];
        float conf_loss = (gf + sf) * (1.f / (float)Nn);
        g_focal[b] = 0.f;                  // reset for next replay
        float box = (nn > 0) ? __fdividef(sc, (float)nn) : 0.f;
        atomicAdd(out, (conf_loss + box) * (1.f / (float)Bn));
    }
}

extern "C" void kernel_launch(void* const* d_in, const int* in_sizes, int n_in,
                              void* d_out, int out_size) {
    const float* preds   = (const float*)d_in[0];
    const float* targets = (const float*)d_in[1];
    float* out = (float*)d_out;

    k_main <<<dim3(NTILES, Bn), 256>>>(preds, targets, out);
    k_final<<<Bn, Mn>>>(preds, targets, out);
}

// round 10
// speedup vs baseline: 3.7867x; 1.0022x over previous
#include <cuda_runtime.h>
#include <math.h>

#define Bn 16
#define Nn 25000
#define Mn 64
#define TILE 128
#define NTILES ((Nn + TILE - 1) / TILE)   // 196

// ---- scratch (no allocations allowed; zero-initialized at load) ----
// g_pack maintained by atomicMax (idempotent across replays), reset by k_final.
__device__ unsigned long long g_pack[Bn*Mn];   // (iou_bits<<32) | ~idx
__device__ float g_focal[Bn];

// One 128-pred tile per block (256 threads). Lane l of each warp owns targets
// l and l+32 in registers; warp w streams preds [w*16, w*16+16) via broadcast
// LDS. Argmax tracked by packing k (4 bits) into the CLEARED low mantissa bits
// of iou and a single FMAX — no predicates, no index registers in the hot loop.
__global__ __launch_bounds__(256, 6) void k_main(const float* __restrict__ preds,
                                                 const float* __restrict__ targets,
                                                 float* __restrict__ out) {
    const int b    = blockIdx.y;
    const int base = blockIdx.x * TILE;
    const int tid  = threadIdx.x;
    const int lane = tid & 31;
    const int warp = tid >> 5;

    __shared__ float4 s_box[TILE];
    __shared__ float  s_area[TILE];
    __shared__ unsigned long long s_m[8*Mn];
    __shared__ float  s_red[8];

    // zero the output for k_final's atomicAdd (stream order makes this safe)
    if (b == 0 && blockIdx.x == 0 && tid == 96) out[0] = 0.f;

    const float4 t0 = __ldg((const float4*)targets + (b*Mn + lane));
    const float4 t1 = __ldg((const float4*)targets + (b*Mn + lane + 32));
    const float ta0 = (t0.z - t0.x) * (t0.w - t0.y);
    const float ta1 = (t1.z - t1.x) * (t1.w - t1.y);

    const int cnt = min(TILE, Nn - base);
    float facc = 0.f;
    if (tid < TILE) {
        // stage + convert + focal(target=0), fast-math (budget 1e-3, err ~1e-6)
        float x1, y1, x2, y2, area;
        if (tid < cnt) {
            const float* pr = preds + ((size_t)b * Nn + base + tid) * 5;
            float cx = pr[0], cy = pr[1];
            float w = fmaxf(pr[2], 1e-4f), h = fmaxf(pr[3], 1e-4f);
            float conf = pr[4];
            x1 = cx - 0.5f * w; x2 = cx + 0.5f * w;
            y1 = cy - 0.5f * h; y2 = cy + 0.5f * h;
            area = (x2 - x1) * (y2 - y1);
            // focal(target=0): 0.75 * clamp(sigmoid)^2 * softplus(conf)
            float en  = __expf(-fabsf(conf));           // e^{-|c|} in (0,1]
            float ce  = fmaxf(conf, 0.f) + __logf(1.f + en);
            float rp  = __fdividef(1.f, 1.f + en);
            float p   = (conf >= 0.f) ? rp : 1.f - rp;  // sigmoid(conf)
            float om  = fminf(fmaxf(p, 1e-6f), 1.f - 1e-6f);
            facc = 0.75f * om * om * ce;
        } else {
            // pad: degenerate far box -> iou exactly 0; loses all real ties
            x1 = y1 = x2 = y2 = -3e8f; area = 0.f;
        }
        s_box[tid]  = make_float4(x1, y1, x2, y2);
        s_area[tid] = area;
    }
    __syncthreads();

    // best = float whose bits are ((iou_bits & ~15) | k); iou >= 0 so FMAX
    // ordering == unsigned ordering. Masking costs <=15 ulp (~2e-6 rel) noise.
    float best0 = 0.f, best1 = 0.f;
    const int pbase = base + warp * 16;

    #pragma unroll
    for (int k = 0; k < 16; k++) {
        const float4 bx = s_box[warp * 16 + k];   // broadcast LDS
        const float  ar = s_area[warp * 16 + k];
        {
            float iw = fmaxf(fminf(bx.z, t0.z) - fmaxf(bx.x, t0.x), 0.f);
            float ih = fmaxf(fminf(bx.w, t0.w) - fmaxf(bx.y, t0.y), 0.f);
            float inter = iw * ih;
            float iou = __fdividef(inter, ar + ta0 - inter);
            unsigned cbits = (__float_as_uint(iou) & ~15u) | (unsigned)k;
            best0 = fmaxf(best0, __uint_as_float(cbits));
        }
        {
            float iw = fmaxf(fminf(bx.z, t1.z) - fmaxf(bx.x, t1.x), 0.f);
            float ih = fmaxf(fminf(bx.w, t1.w) - fmaxf(bx.y, t1.y), 0.f);
            float inter = iw * ih;
            float iou = __fdividef(inter, ar + ta1 - inter);
            unsigned cbits = (__float_as_uint(iou) & ~15u) | (unsigned)k;
            best1 = fmaxf(best1, __uint_as_float(cbits));
        }
    }

    // decode k from the low 4 bits; keep the (masked) iou bits as the value
    const unsigned ub0 = __float_as_uint(best0);
    const unsigned ub1 = __float_as_uint(best1);
    const int bi0 = pbase + (int)(ub0 & 15u);
    const int bi1 = pbase + (int)(ub1 & 15u);

    // pack: higher iou wins; on exact tie, ~idx makes SMALLER idx win
    s_m[warp*Mn + lane]      = ((unsigned long long)ub0 << 32) | (unsigned)(~bi0);
    s_m[warp*Mn + lane + 32] = ((unsigned long long)ub1 << 32) | (unsigned)(~bi1);

    // focal warp-reduce
    #pragma unroll
    for (int off = 16; off; off >>= 1)
        facc += __shfl_xor_sync(0xffffffffu, facc, off);
    if (lane == 0) s_red[warp] = facc;
    __syncthreads();

    if (tid < Mn) {
        unsigned long long bv = 0ull;
        #pragma unroll
        for (int w = 0; w < 8; w++) {
            unsigned long long v = s_m[w*Mn + tid];
            bv = (v > bv) ? v : bv;
        }
        atomicMax(&g_pack[b*Mn + tid], bv);
    }
    if (tid == 64) {
        float s = 0.f;
        #pragma unroll
        for (int w = 0; w < 8; w++) s += s_red[w];
        atomicAdd(&g_focal[b], s);
    }
}

// Latency-lean tail: one image per block (16 x 64). All loads prefetched
// before the dedup; unconditional compute with masked accumulate; fast-math
// intrinsics; shuffle reductions.  (UNCHANGED — ~8us ncu, validated R8)
__global__ __launch_bounds__(64) void k_final(const float* __restrict__ preds,
                                              const float* __restrict__ targets,
                                              float* __restrict__ out) {
    const int b    = blockIdx.x;
    const int m    = threadIdx.x;
    const int lane = m & 31;
    const int w    = m >> 5;

    __shared__ float s_iou[Mn];
    __shared__ int   s_idx[Mn];
    __shared__ float s_c[2], s_f[2];
    __shared__ int   s_n[2];

    // --- independent prefetches (issue ASAP) ---
    const float gf = g_focal[b];                         // broadcast load
    unsigned long long v = g_pack[b*Mn + m];
    g_pack[b*Mn + m] = 0ull;                             // reset for next replay
    const float iou_b = __uint_as_float((unsigned)(v >> 32));
    int idx = (int)(~(unsigned)v);
    idx = min(max(idx, 0), Nn - 1);                      // pad-safe clamp

    // prefetch the matched pred (overlaps the dedup below)
    const float* pr = preds + ((size_t)b*Nn + idx) * 5;
    const float cx = pr[0], cy = pr[1];
    const float pw = fmaxf(pr[2], 1e-4f), ph = fmaxf(pr[3], 1e-4f);
    const float conf = pr[4];
    const float4 t = __ldg((const float4*)targets + (b*Mn + m));

    s_iou[m] = iou_b;
    s_idx[m] = idx;
    __syncthreads();

    // greedy dedup, closed form
    bool ok = iou_b > 0.2f;
    for (int mp = 0; mp < m; mp++)
        ok = ok && !(s_idx[mp] == idx && s_iou[mp] > 0.2f);

    // --- unconditional CIoU + focal correction, masked at accumulate ---
    const float x1p = cx - 0.5f*pw, x2p = cx + 0.5f*pw;
    const float y1p = cy - 0.5f*ph, y2p = cy + 0.5f*ph;
    const float x1t = t.x, y1t = t.y, x2t = t.z, y2t = t.w;

    float inter = fmaxf(fminf(x2p,x2t) - fmaxf(x1p,x1t), 0.f)
                * fmaxf(fminf(y2p,y2t) - fmaxf(y1p,y1t), 0.f);
    float un  = (x2p-x1p)*(y2p-y1p) + (x2t-x1t)*(y2t-y1t) - inter;
    float iou = __fdividef(inter, un + 1e-7f);
    float cw = fmaxf(x2p,x2t) - fminf(x1p,x1t);
    float ch = fmaxf(y2p,y2t) - fminf(y1p,y1t);
    float diag = cw*cw + ch*ch + 1e-7f;
    float dx = x1p + x2p - x1t - x2t;
    float dy = y1p + y2p - y1t - y2t;
    float centers = (dx*dx + dy*dy) * 0.25f;
    float wp = x2p - x1p, hp = y2p - y1p;
    float wt = x2t - x1t, ht = y2t - y1t;
    float dv = atanf(__fdividef(wt, ht)) - atanf(__fdividef(wp, hp));
    float vv = (float)(4.0/(M_PI*M_PI)) * dv * dv;
    float alpha = __fdividef(vv, 1.f - iou + vv + 1e-7f);
    float ci = 1.f - iou + __fdividef(centers, diag) + alpha*vv;

    // focal(target=1) - focal(target=0) correction
    float pp  = __fdividef(1.f, 1.f + __expf(-conf));
    float l1e = __logf(1.f + __expf(-fabsf(conf)));
    float ce1 = fmaxf(conf, 0.f) - conf + l1e;
    float ce0 = fmaxf(conf, 0.f) + l1e;
    float pt1 = fminf(fmaxf(pp,       1e-6f), 1.f - 1e-6f);
    float pt0 = fminf(fmaxf(1.f - pp, 1e-6f), 1.f - 1e-6f);
    float a1 = 1.f - pt1, a0 = 1.f - pt0;
    float fd = 0.25f*a1*a1*ce1 - 0.75f*a0*a0*ce0;

    const float msk = ok ? 1.f : 0.f;
    ci *= msk; fd *= msk;
    int n = ok ? 1 : 0;

    // two-warp shuffle reduction
    #pragma unroll
    for (int off = 16; off; off >>= 1) {
        ci += __shfl_xor_sync(0xffffffffu, ci, off);
        fd += __shfl_xor_sync(0xffffffffu, fd, off);
        n  += __shfl_xor_sync(0xffffffffu, n,  off);
    }
    if (lane == 0) { s_c[w] = ci; s_f[w] = fd; s_n[w] = n; }
    __syncthreads();

    if (m == 0) {
        float sc = s_c[0] + s_c[1];
        float sf = s_f[0] + s_f[1];
        int   nn = s_n[0] + s_n[1];
        float conf_loss = (gf + sf) * (1.f / (float)Nn);
        g_focal[b] = 0.f;                  // reset for next replay
        float box = (nn > 0) ? __fdividef(sc, (float)nn) : 0.f;
        atomicAdd(out, (conf_loss + box) * (1.f / (float)Bn));
    }
}

extern "C" void kernel_launch(void* const* d_in, const int* in_sizes, int n_in,
                              void* d_out, int out_size) {
    const float* preds   = (const float*)d_in[0];
    const float* targets = (const float*)d_in[1];
    float* out = (float*)d_out;

    k_main <<<dim3(NTILES, Bn), 256>>>(preds, targets, out);
    k_final<<<Bn, Mn>>>(preds, targets, out);
}

// round 11
// speedup vs baseline: 3.8200x; 1.0088x over previous
#include <cuda_runtime.h>
#include <math.h>

#define Bn 16
#define Nn 25000
#define Mn 64
#define TILE 256
#define NTILES ((Nn + TILE - 1) / TILE)   // 98

// ---- scratch (no allocations allowed; zero-initialized at load) ----
// g_pack maintained by atomicMax (idempotent across replays), reset by k_final.
__device__ unsigned long long g_pack[Bn*Mn];   // (iou_bits<<32) | ~idx
__device__ float g_focal[Bn];

// One 256-pred tile per block. Lane l of each warp owns targets l and l+32.
// Each iteration streams TWO preds (k, k+16) of this warp's 32-pred stripe ->
// 4 independent IoU chains per lane for latency hiding. Argmax tracked by
// packing the 5-bit pred slot into the cleared low mantissa bits + FMAX.
__global__ __launch_bounds__(256) void k_main(const float* __restrict__ preds,
                                              const float* __restrict__ targets,
                                              float* __restrict__ out) {
    const int b    = blockIdx.y;
    const int base = blockIdx.x * TILE;
    const int tid  = threadIdx.x;
    const int lane = tid & 31;
    const int warp = tid >> 5;

    __shared__ float4 s_box[TILE];
    __shared__ float  s_area[TILE];
    __shared__ unsigned long long s_m[8*Mn];
    __shared__ float  s_red[8];

    // zero the output for k_final's atomicAdd (stream order makes this safe)
    if (b == 0 && blockIdx.x == 0 && tid == 96) out[0] = 0.f;

    const float4 t0 = __ldg((const float4*)targets + (b*Mn + lane));
    const float4 t1 = __ldg((const float4*)targets + (b*Mn + lane + 32));
    const float ta0 = (t0.z - t0.x) * (t0.w - t0.y);
    const float ta1 = (t1.z - t1.x) * (t1.w - t1.y);

    const int cnt = min(TILE, Nn - base);
    float facc = 0.f;
    {
        // stage + convert + focal(target=0), fast-math (budget 1e-3, err ~1e-6)
        float x1, y1, x2, y2, area;
        if (tid < cnt) {
            const float* pr = preds + ((size_t)b * Nn + base + tid) * 5;
            float cx = pr[0], cy = pr[1];
            float w = fmaxf(pr[2], 1e-4f), h = fmaxf(pr[3], 1e-4f);
            float conf = pr[4];
            x1 = cx - 0.5f * w; x2 = cx + 0.5f * w;
            y1 = cy - 0.5f * h; y2 = cy + 0.5f * h;
            area = (x2 - x1) * (y2 - y1);
            // focal(target=0): 0.75 * clamp(sigmoid)^2 * softplus(conf)
            float en  = __expf(-fabsf(conf));           // e^{-|c|} in (0,1]
            float ce  = fmaxf(conf, 0.f) + __logf(1.f + en);
            float rp  = __fdividef(1.f, 1.f + en);
            float p   = (conf >= 0.f) ? rp : 1.f - rp;  // sigmoid(conf)
            float om  = fminf(fmaxf(p, 1e-6f), 1.f - 1e-6f);
            facc = 0.75f * om * om * ce;
        } else {
            // pad: degenerate far box -> iou exactly 0; loses all real ties
            x1 = y1 = x2 = y2 = -3e8f; area = 0.f;
        }
        s_box[tid]  = make_float4(x1, y1, x2, y2);
        s_area[tid] = area;
    }
    __syncthreads();

    // best = float whose bits are ((iou_bits & ~31) | slot); iou >= 0 so FMAX
    // ordering == unsigned ordering. Masking costs <=31 ulp (~4e-6 rel) noise.
    float best0 = 0.f, best1 = 0.f;
    const int pbase = base + warp * 32;

    #pragma unroll
    for (int k = 0; k < 16; k++) {
        const float4 bxA = s_box[warp * 32 + k];        // broadcast LDS
        const float  arA = s_area[warp * 32 + k];
        const float4 bxB = s_box[warp * 32 + k + 16];
        const float  arB = s_area[warp * 32 + k + 16];

        // chain A0
        {
            float iw = fmaxf(fminf(bxA.z, t0.z) - fmaxf(bxA.x, t0.x), 0.f);
            float ih = fmaxf(fminf(bxA.w, t0.w) - fmaxf(bxA.y, t0.y), 0.f);
            float inter = iw * ih;
            float iou = __fdividef(inter, arA + ta0 - inter);
            unsigned cb = (__float_as_uint(iou) & ~31u) | (unsigned)k;
            best0 = fmaxf(best0, __uint_as_float(cb));
        }
        // chain B0
        {
            float iw = fmaxf(fminf(bxB.z, t0.z) - fmaxf(bxB.x, t0.x), 0.f);
            float ih = fmaxf(fminf(bxB.w, t0.w) - fmaxf(bxB.y, t0.y), 0.f);
            float inter = iw * ih;
            float iou = __fdividef(inter, arB + ta0 - inter);
            unsigned cb = (__float_as_uint(iou) & ~31u) | (unsigned)(k + 16);
            best0 = fmaxf(best0, __uint_as_float(cb));
        }
        // chain A1
        {
            float iw = fmaxf(fminf(bxA.z, t1.z) - fmaxf(bxA.x, t1.x), 0.f);
            float ih = fmaxf(fminf(bxA.w, t1.w) - fmaxf(bxA.y, t1.y), 0.f);
            float inter = iw * ih;
            float iou = __fdividef(inter, arA + ta1 - inter);
            unsigned cb = (__float_as_uint(iou) & ~31u) | (unsigned)k;
            best1 = fmaxf(best1, __uint_as_float(cb));
        }
        // chain B1
        {
            float iw = fmaxf(fminf(bxB.z, t1.z) - fmaxf(bxB.x, t1.x), 0.f);
            float ih = fmaxf(fminf(bxB.w, t1.w) - fmaxf(bxB.y, t1.y), 0.f);
            float inter = iw * ih;
            float iou = __fdividef(inter, arB + ta1 - inter);
            unsigned cb = (__float_as_uint(iou) & ~31u) | (unsigned)(k + 16);
            best1 = fmaxf(best1, __uint_as_float(cb));
        }
    }

    // decode slot from the low 5 bits; keep the (masked) iou bits as the value
    const unsigned ub0 = __float_as_uint(best0);
    const unsigned ub1 = __float_as_uint(best1);
    const int bi0 = pbase + (int)(ub0 & 31u);
    const int bi1 = pbase + (int)(ub1 & 31u);

    // pack: higher iou wins; on exact tie, ~idx makes SMALLER idx win
    s_m[warp*Mn + lane]      = ((unsigned long long)ub0 << 32) | (unsigned)(~bi0);
    s_m[warp*Mn + lane + 32] = ((unsigned long long)ub1 << 32) | (unsigned)(~bi1);

    // focal warp-reduce
    #pragma unroll
    for (int off = 16; off; off >>= 1)
        facc += __shfl_xor_sync(0xffffffffu, facc, off);
    if (lane == 0) s_red[warp] = facc;
    __syncthreads();

    if (tid < Mn) {
        unsigned long long bv = 0ull;
        #pragma unroll
        for (int w = 0; w < 8; w++) {
            unsigned long long v = s_m[w*Mn + tid];
            bv = (v > bv) ? v : bv;
        }
        atomicMax(&g_pack[b*Mn + tid], bv);
    }
    if (tid == 64) {
        float s = 0.f;
        #pragma unroll
        for (int w = 0; w < 8; w++) s += s_red[w];
        atomicAdd(&g_focal[b], s);
    }
}

// Latency-lean tail: one image per block (16 x 64). All loads prefetched
// before the dedup; unconditional compute with masked accumulate; fast-math
// intrinsics; shuffle reductions.  (UNCHANGED — ~8us ncu, validated R8/R10)
__global__ __launch_bounds__(64) void k_final(const float* __restrict__ preds,
                                              const float* __restrict__ targets,
                                              float* __restrict__ out) {
    const int b    = blockIdx.x;
    const int m    = threadIdx.x;
    const int lane = m & 31;
    const int w    = m >> 5;

    __shared__ float s_iou[Mn];
    __shared__ int   s_idx[Mn];
    __shared__ float s_c[2], s_f[2];
    __shared__ int   s_n[2];

    // --- independent prefetches (issue ASAP) ---
    const float gf = g_focal[b];                         // broadcast load
    unsigned long long v = g_pack[b*Mn + m];
    g_pack[b*Mn + m] = 0ull;                             // reset for next replay
    const float iou_b = __uint_as_float((unsigned)(v >> 32));
    int idx = (int)(~(unsigned)v);
    idx = min(max(idx, 0), Nn - 1);                      // pad-safe clamp

    // prefetch the matched pred (overlaps the dedup below)
    const float* pr = preds + ((size_t)b*Nn + idx) * 5;
    const float cx = pr[0], cy = pr[1];
    const float pw = fmaxf(pr[2], 1e-4f), ph = fmaxf(pr[3], 1e-4f);
    const float conf = pr[4];
    const float4 t = __ldg((const float4*)targets + (b*Mn + m));

    s_iou[m] = iou_b;
    s_idx[m] = idx;
    __syncthreads();

    // greedy dedup, closed form
    bool ok = iou_b > 0.2f;
    for (int mp = 0; mp < m; mp++)
        ok = ok && !(s_idx[mp] == idx && s_iou[mp] > 0.2f);

    // --- unconditional CIoU + focal correction, masked at accumulate ---
    const float x1p = cx - 0.5f*pw, x2p = cx + 0.5f*pw;
    const float y1p = cy - 0.5f*ph, y2p = cy + 0.5f*ph;
    const float x1t = t.x, y1t = t.y, x2t = t.z, y2t = t.w;

    float inter = fmaxf(fminf(x2p,x2t) - fmaxf(x1p,x1t), 0.f)
                * fmaxf(fminf(y2p,y2t) - fmaxf(y1p,y1t), 0.f);
    float un  = (x2p-x1p)*(y2p-y1p) + (x2t-x1t)*(y2t-y1t) - inter;
    float iou = __fdividef(inter, un + 1e-7f);
    float cw = fmaxf(x2p,x2t) - fminf(x1p,x1t);
    float ch = fmaxf(y2p,y2t) - fminf(y1p,y1t);
    float diag = cw*cw + ch*ch + 1e-7f;
    float dx = x1p + x2p - x1t - x2t;
    float dy = y1p + y2p - y1t - y2t;
    float centers = (dx*dx + dy*dy) * 0.25f;
    float wp = x2p - x1p, hp = y2p - y1p;
    float wt = x2t - x1t, ht = y2t - y1t;
    float dv = atanf(__fdividef(wt, ht)) - atanf(__fdividef(wp, hp));
    float vv = (float)(4.0/(M_PI*M_PI)) * dv * dv;
    float alpha = __fdividef(vv, 1.f - iou + vv + 1e-7f);
    float ci = 1.f - iou + __fdividef(centers, diag) + alpha*vv;

    // focal(target=1) - focal(target=0) correction
    float pp  = __fdividef(1.f, 1.f + __expf(-conf));
    float l1e = __logf(1.f + __expf(-fabsf(conf)));
    float ce1 = fmaxf(conf, 0.f) - conf + l1e;
    float ce0 = fmaxf(conf, 0.f) + l1e;
    float pt1 = fminf(fmaxf(pp,       1e-6f), 1.f - 1e-6f);
    float pt0 = fminf(fmaxf(1.f - pp, 1e-6f), 1.f - 1e-6f);
    float a1 = 1.f - pt1, a0 = 1.f - pt0;
    float fd = 0.25f*a1*a1*ce1 - 0.75f*a0*a0*ce0;

    const float msk = ok ? 1.f : 0.f;
    ci *= msk; fd *= msk;
    int n = ok ? 1 : 0;

    // two-warp shuffle reduction
    #pragma unroll
    for (int off = 16; off; off >>= 1) {
        ci += __shfl_xor_sync(0xffffffffu, ci, off);
        fd += __shfl_xor_sync(0xffffffffu, fd, off);
        n  += __shfl_xor_sync(0xffffffffu, n,  off);
    }
    if (lane == 0) { s_c[w] = ci; s_f[w] = fd; s_n[w] = n; }
    __syncthreads();

    if (m == 0) {
        float sc = s_c[0] + s_c[1];
        float sf = s_f[0] + s_f[1];
        int   nn = s_n[0] + s_n[1];
        float conf_loss = (gf + sf) * (1.f / (float)Nn);
        g_focal[b] = 0.f;                  // reset for next replay
        float box = (nn > 0) ? __fdividef(sc, (float)nn) : 0.f;
        atomicAdd(out, (conf_loss + box) * (1.f / (float)Bn));
    }
}

extern "C" void kernel_launch(void* const* d_in, const int* in_sizes, int n_in,
                              void* d_out, int out_size) {
    const float* preds   = (const float*)d_in[0];
    const float* targets = (const float*)d_in[1];
    float* out = (float*)d_out;

    k_main <<<dim3(NTILES, Bn), 256>>>(preds, targets, out);
    k_final<<<Bn, Mn>>>(preds, targets, out);
}